// round 10
// baseline (speedup 1.0000x reference)
#include <cuda_runtime.h>
#include <cuda_bf16.h>
#include <cstdint>

#define D 128
#define ALPHA 0.5f
#define MAX_NODES 50000
#define MAX_EDGES 800000
#define NB 592            // persistent grid: 4 CTAs/SM on 148 SMs, all co-resident
#define NT 256

// ---------------- scratch (static device globals; no allocation) ----------------
__device__ float g_y_src[(size_t)MAX_NODES * D];   // alpha * (x @ W_src)
__device__ float g_y_dst[(size_t)MAX_NODES * D];   // (1-alpha) * (x @ W_dst)
__device__ int   g_outdeg[MAX_NODES];
__device__ int   g_indeg[MAX_NODES];
__device__ float g_dout[MAX_NODES];
__device__ float g_din[MAX_NODES];
__device__ int   g_ei[2 * MAX_EDGES];

// software global barrier state (generation-based; self-resetting)
__device__ unsigned g_cnt = 0;
__device__ volatile unsigned g_gen = 0;

__device__ __forceinline__ void grid_barrier(int nblocks) {
    __syncthreads();
    if (threadIdx.x == 0) {
        unsigned my = g_gen;
        __threadfence();
        if (atomicAdd(&g_cnt, 1u) == (unsigned)(nblocks - 1)) {
            g_cnt = 0;
            __threadfence();
            g_gen = my + 1;
        } else {
            while (g_gen == my) { }
        }
        __threadfence();
    }
    __syncthreads();
}

// Dtype-agnostic index decode (exact for int32 and float32 encodings).
__device__ __forceinline__ int decode_idx(int v, int n) {
    if ((unsigned)v < (unsigned)n) return v;
    float f = __int_as_float(v);
    int r = (f > 0.0f) ? (int)f : 0;
    return ((unsigned)r < (unsigned)n) ? r : 0;
}

#define GEMM_TR 32
#define GEMM_KT 32

__global__ void __launch_bounds__(NT, 4)
fused_kernel(const float* __restrict__ x,
             const int* __restrict__ ei_raw,
             const float* __restrict__ W_src, const float* __restrict__ b_src,
             const float* __restrict__ W_dst, const float* __restrict__ b_dst,
             float* __restrict__ out,
             int N, int E) {
    __shared__ float Ws[GEMM_KT][D];         // 16 KB
    __shared__ float Xs[GEMM_TR][GEMM_KT];   // 4 KB

    const int tid = threadIdx.x;
    const int nb = gridDim.x;
    const int gstride = nb * NT;
    const int gtid = blockIdx.x * NT + tid;

    // ---------------- phase 1: bias -> out (float4); zero degree counters --------
    {
        int total4 = N * (D / 4);
        for (int i = gtid; i < total4; i += gstride) {
            int d = (i & (D / 4 - 1)) * 4;
            float4 b4 = make_float4(
                ALPHA * b_src[d + 0] + (1.0f - ALPHA) * b_dst[d + 0],
                ALPHA * b_src[d + 1] + (1.0f - ALPHA) * b_dst[d + 1],
                ALPHA * b_src[d + 2] + (1.0f - ALPHA) * b_dst[d + 2],
                ALPHA * b_src[d + 3] + (1.0f - ALPHA) * b_dst[d + 3]);
            ((float4*)out)[i] = b4;
        }
    }
    for (int i = gtid; i < N; i += gstride) {
        g_outdeg[i] = 0;
        g_indeg[i] = 0;
    }
    grid_barrier(nb);

    // ---------------- phase 2a: decode edge index + count degrees ----------------
    for (int i = gtid; i < 2 * E; i += gstride) {
        int v = decode_idx(ei_raw[i], N);
        g_ei[i] = v;
        if (i < E) atomicAdd(&g_outdeg[v], 1);
        else       atomicAdd(&g_indeg[v], 1);
    }

    // ---------------- phase 2b: two GEMMs, tile jobs over blocks -----------------
    // 32-row tiles; thread (c=tid&31, rg=tid>>5) -> rows {rg+8j, j<4}, cols {4c..}
    {
        const int tiles = (N + GEMM_TR - 1) / GEMM_TR;
        const int c  = tid & 31;
        const int rg = tid >> 5;
        for (int job = blockIdx.x; job < 2 * tiles; job += nb) {
            const bool is_src = (job < tiles);
            const float* W = is_src ? W_src : W_dst;
            float* Y       = is_src ? g_y_src : g_y_dst;
            const float scale = is_src ? ALPHA : (1.0f - ALPHA);
            const int row0 = (is_src ? job : job - tiles) * GEMM_TR;

            float acc[4][4];
#pragma unroll
            for (int j = 0; j < 4; j++)
#pragma unroll
                for (int q = 0; q < 4; q++) acc[j][q] = 0.0f;

            for (int kt = 0; kt < D; kt += GEMM_KT) {
#pragma unroll
                for (int i = tid; i < GEMM_KT * D; i += NT) {
                    int kk = i >> 7, dd = i & (D - 1);
                    Ws[kk][dd] = W[(kt + kk) * D + dd];
                }
#pragma unroll
                for (int i = tid; i < GEMM_TR * GEMM_KT; i += NT) {
                    int r = i / GEMM_KT, kk = i % GEMM_KT;
                    int gr = row0 + r;
                    Xs[r][kk] = (gr < N) ? x[(size_t)gr * D + kt + kk] : 0.0f;
                }
                __syncthreads();
#pragma unroll
                for (int k = 0; k < GEMM_KT; k++) {
                    float4 w4 = *(const float4*)&Ws[k][c * 4];
#pragma unroll
                    for (int j = 0; j < 4; j++) {
                        float xv = Xs[rg + 8 * j][k];
                        acc[j][0] += xv * w4.x;
                        acc[j][1] += xv * w4.y;
                        acc[j][2] += xv * w4.z;
                        acc[j][3] += xv * w4.w;
                    }
                }
                __syncthreads();
            }
#pragma unroll
            for (int j = 0; j < 4; j++) {
                int r = row0 + rg + 8 * j;
                if (r < N) {
                    float4 o = make_float4(scale * acc[j][0], scale * acc[j][1],
                                           scale * acc[j][2], scale * acc[j][3]);
                    *(float4*)&Y[(size_t)r * D + c * 4] = o;
                }
            }
        }
    }
    grid_barrier(nb);

    // ---------------- phase 3: inverse-sqrt degrees ------------------------------
    for (int i = gtid; i < N; i += gstride) {
        int od = g_outdeg[i];
        int id = g_indeg[i];
        g_dout[i] = (od > 0) ? rsqrtf((float)od) : 0.0f;
        g_din[i]  = (id > 0) ? rsqrtf((float)id) : 0.0f;
    }
    grid_barrier(nb);

    // ---------------- phase 4: bidirectional scatter, 2 edges / warp-iter --------
    {
        const int lane = tid & 31;
        const int wpb = NT / 32;
        const int wid = blockIdx.x * wpb + (tid >> 5);
        const int wstride = nb * wpb;
        const float4* ys = (const float4*)g_y_src;
        const float4* yd = (const float4*)g_y_dst;

        int e = wid * 2;
        const int estep = wstride * 2;
        for (; e + 1 < E; e += estep) {
            int row0 = g_ei[e],     col0 = g_ei[E + e];
            int row1 = g_ei[e + 1], col1 = g_ei[E + e + 1];
            float w0 = g_dout[row0] * g_din[col0];
            float w1 = g_dout[row1] * g_din[col1];

            float4 a0 = ys[col0 * 32 + lane];
            float4 b0 = yd[row0 * 32 + lane];
            float4 a1 = ys[col1 * 32 + lane];
            float4 b1 = yd[row1 * 32 + lane];

            float* p0 = out + (size_t)row0 * D + lane * 4;
            float* q0 = out + (size_t)col0 * D + lane * 4;
            float* p1 = out + (size_t)row1 * D + lane * 4;
            float* q1 = out + (size_t)col1 * D + lane * 4;

            asm volatile("red.global.add.v4.f32 [%0], {%1, %2, %3, %4};"
                         :: "l"(p0), "f"(w0 * a0.x), "f"(w0 * a0.y),
                            "f"(w0 * a0.z), "f"(w0 * a0.w) : "memory");
            asm volatile("red.global.add.v4.f32 [%0], {%1, %2, %3, %4};"
                         :: "l"(q0), "f"(w0 * b0.x), "f"(w0 * b0.y),
                            "f"(w0 * b0.z), "f"(w0 * b0.w) : "memory");
            asm volatile("red.global.add.v4.f32 [%0], {%1, %2, %3, %4};"
                         :: "l"(p1), "f"(w1 * a1.x), "f"(w1 * a1.y),
                            "f"(w1 * a1.z), "f"(w1 * a1.w) : "memory");
            asm volatile("red.global.add.v4.f32 [%0], {%1, %2, %3, %4};"
                         :: "l"(q1), "f"(w1 * b1.x), "f"(w1 * b1.y),
                            "f"(w1 * b1.z), "f"(w1 * b1.w) : "memory");
        }
        if (e < E) {
            int row = g_ei[e], col = g_ei[E + e];
            float w = g_dout[row] * g_din[col];
            float4 a = ys[col * 32 + lane];
            float4 b = yd[row * 32 + lane];
            float* po = out + (size_t)row * D + lane * 4;
            float* qo = out + (size_t)col * D + lane * 4;
            asm volatile("red.global.add.v4.f32 [%0], {%1, %2, %3, %4};"
                         :: "l"(po), "f"(w * a.x), "f"(w * a.y),
                            "f"(w * a.z), "f"(w * a.w) : "memory");
            asm volatile("red.global.add.v4.f32 [%0], {%1, %2, %3, %4};"
                         :: "l"(qo), "f"(w * b.x), "f"(w * b.y),
                            "f"(w * b.z), "f"(w * b.w) : "memory");
        }
    }
}

// ---------------- launch --------------------------------------------------------
extern "C" void kernel_launch(void* const* d_in, const int* in_sizes, int n_in,
                              void* d_out, int out_size) {
    // Size-based input identification (order-proof).
    int idx_x = -1, idx_e = -1;
    int idxW[2] = {-1, -1}, idxB[2] = {-1, -1};
    int nw = 0, nb_ = 0;
    for (int i = 0; i < n_in; i++) {
        int s = in_sizes[i];
        if (s == out_size && idx_x < 0) idx_x = i;
        else if (s == D * D && nw < 2)  idxW[nw++] = i;
        else if (s == D && nb_ < 2)     idxB[nb_++] = i;
        else if (idx_e < 0)             idx_e = i;
    }
    bool src_first = (idx_x < idx_e);

    const float* x      = (const float*)d_in[idx_x];
    const int*   ei_raw = (const int*)d_in[idx_e];
    const float* W_src  = (const float*)d_in[src_first ? idxW[0] : idxW[1]];
    const float* W_dst  = (const float*)d_in[src_first ? idxW[1] : idxW[0]];
    const float* b_src  = (const float*)d_in[src_first ? idxB[0] : idxB[1]];
    const float* b_dst  = (const float*)d_in[src_first ? idxB[1] : idxB[0]];
    float* out = (float*)d_out;

    int N = out_size / D;            // 50000
    int E = in_sizes[idx_e] / 2;     // 800000
    if (E > MAX_EDGES) E = MAX_EDGES;

    // ONE launch: all phases inside, separated by grid barriers.
    fused_kernel<<<NB, NT>>>(x, ei_raw, W_src, b_src, W_dst, b_dst, out, N, E);
}

// round 11
// speedup vs baseline: 1.3345x; 1.3345x over previous
#include <cuda_runtime.h>
#include <cuda_bf16.h>
#include <cstdint>

#define D 128
#define ALPHA 0.5f
#define MAX_NODES 50000
#define MAX_EDGES 800000
#define NB 296            // persistent grid: 2 CTAs/SM on 148 SMs, all co-resident
#define NT 256

// ---------------- scratch (static device globals; no allocation) ----------------
__device__ float g_y_src[(size_t)MAX_NODES * D];   // alpha * (x @ W_src)
__device__ float g_y_dst[(size_t)MAX_NODES * D];   // (1-alpha) * (x @ W_dst)
__device__ int   g_outdeg[MAX_NODES];
__device__ int   g_indeg[MAX_NODES];
__device__ float g_dout[MAX_NODES];
__device__ float g_din[MAX_NODES];
__device__ int   g_ei[2 * MAX_EDGES];
// CSR structures (bucket ranges are disjoint but unordered across nodes)
__device__ int   g_rs[MAX_NODES];      // forward bucket start (by row)
__device__ int   g_cs[MAX_NODES];      // backward bucket start (by col)
__device__ int   g_rcur[MAX_NODES];    // fill cursors
__device__ int   g_ccur[MAX_NODES];
__device__ int   g_fwd[MAX_EDGES];     // col indices, bucketed by row
__device__ int   g_bwd[MAX_EDGES];     // row indices, bucketed by col
__device__ unsigned g_base_f = 0, g_base_b = 0;

// software global barrier state (generation-based; self-resetting)
__device__ unsigned g_cnt = 0;
__device__ volatile unsigned g_gen = 0;

__device__ __forceinline__ void grid_barrier(int nblocks) {
    __syncthreads();
    if (threadIdx.x == 0) {
        unsigned my = g_gen;
        __threadfence();
        if (atomicAdd(&g_cnt, 1u) == (unsigned)(nblocks - 1)) {
            g_cnt = 0;
            __threadfence();
            g_gen = my + 1;
        } else {
            while (g_gen == my) { }
        }
        __threadfence();
    }
    __syncthreads();
}

// Dtype-agnostic index decode (exact for int32 and float32 encodings).
__device__ __forceinline__ int decode_idx(int v, int n) {
    if ((unsigned)v < (unsigned)n) return v;
    float f = __int_as_float(v);
    int r = (f > 0.0f) ? (int)f : 0;
    return ((unsigned)r < (unsigned)n) ? r : 0;
}

#define GEMM_TR 64
#define GEMM_KT 32

__global__ void __launch_bounds__(NT, 2)
fused_kernel(const float* __restrict__ x,
             const int* __restrict__ ei_raw,
             const float* __restrict__ W_src, const float* __restrict__ b_src,
             const float* __restrict__ W_dst, const float* __restrict__ b_dst,
             float* __restrict__ out,
             int N, int E) {
    __shared__ float Ws[GEMM_KT][D];        // 16 KB
    __shared__ float Xs[GEMM_TR][GEMM_KT];  // 8 KB

    const int tid = threadIdx.x;
    const int nb = gridDim.x;
    const int gstride = nb * NT;
    const int gtid = blockIdx.x * NT + tid;

    // ---------------- phase 1: zero degree counters + CSR bases ------------------
    for (int i = gtid; i < N; i += gstride) {
        g_outdeg[i] = 0;
        g_indeg[i] = 0;
    }
    if (gtid == 0) { g_base_f = 0; g_base_b = 0; }
    grid_barrier(nb);

    // ---------------- phase 2a: decode edge index + count degrees ----------------
    for (int i = gtid; i < 2 * E; i += gstride) {
        int v = decode_idx(ei_raw[i], N);
        g_ei[i] = v;
        if (i < E) atomicAdd(&g_outdeg[v], 1);
        else       atomicAdd(&g_indeg[v], 1);
    }

    // ---------------- phase 2b: two GEMMs (TR=64 tiles), jobs over blocks --------
    {
        const int tiles = (N + GEMM_TR - 1) / GEMM_TR;
        const int c  = tid & 31;
        const int rg = tid >> 5;
        for (int job = blockIdx.x; job < 2 * tiles; job += nb) {
            const bool is_src = (job < tiles);
            const float* W = is_src ? W_src : W_dst;
            float* Y       = is_src ? g_y_src : g_y_dst;
            const float scale = is_src ? ALPHA : (1.0f - ALPHA);
            const int row0 = (is_src ? job : job - tiles) * GEMM_TR;

            float acc[8][4];
#pragma unroll
            for (int j = 0; j < 8; j++)
#pragma unroll
                for (int q = 0; q < 4; q++) acc[j][q] = 0.0f;

            for (int kt = 0; kt < D; kt += GEMM_KT) {
#pragma unroll
                for (int i = tid; i < GEMM_KT * D; i += NT) {
                    int kk = i >> 7, dd = i & (D - 1);
                    Ws[kk][dd] = W[(kt + kk) * D + dd];
                }
#pragma unroll
                for (int i = tid; i < GEMM_TR * GEMM_KT; i += NT) {
                    int r = i / GEMM_KT, kk = i % GEMM_KT;
                    int gr = row0 + r;
                    Xs[r][kk] = (gr < N) ? x[(size_t)gr * D + kt + kk] : 0.0f;
                }
                __syncthreads();
#pragma unroll
                for (int k = 0; k < GEMM_KT; k++) {
                    float4 w4 = *(const float4*)&Ws[k][c * 4];
#pragma unroll
                    for (int j = 0; j < 8; j++) {
                        float xv = Xs[rg + 8 * j][k];
                        acc[j][0] += xv * w4.x;
                        acc[j][1] += xv * w4.y;
                        acc[j][2] += xv * w4.z;
                        acc[j][3] += xv * w4.w;
                    }
                }
                __syncthreads();
            }
#pragma unroll
            for (int j = 0; j < 8; j++) {
                int r = row0 + rg + 8 * j;
                if (r < N) {
                    float4 o = make_float4(scale * acc[j][0], scale * acc[j][1],
                                           scale * acc[j][2], scale * acc[j][3]);
                    *(float4*)&Y[(size_t)r * D + c * 4] = o;
                }
            }
        }
    }
    grid_barrier(nb);

    // ---------------- phase 3a: degrees -> rsqrt; CSR bucket bases ---------------
    for (int i = gtid; i < N; i += gstride) {
        int od = g_outdeg[i];
        int id = g_indeg[i];
        g_dout[i] = (od > 0) ? rsqrtf((float)od) : 0.0f;
        g_din[i]  = (id > 0) ? rsqrtf((float)id) : 0.0f;
        int rs = (int)atomicAdd(&g_base_f, (unsigned)od);
        int cs = (int)atomicAdd(&g_base_b, (unsigned)id);
        g_rs[i] = rs;  g_rcur[i] = rs;
        g_cs[i] = cs;  g_ccur[i] = cs;
    }
    grid_barrier(nb);

    // ---------------- phase 3b: fill CSR buckets ---------------------------------
    for (int e = gtid; e < E; e += gstride) {
        int row = g_ei[e];
        int col = g_ei[E + e];
        int p = atomicAdd(&g_rcur[row], 1);
        g_fwd[p] = col;
        int q = atomicAdd(&g_ccur[col], 1);
        g_bwd[q] = row;
    }
    grid_barrier(nb);

    // ---------------- phase 4: per-node gather (no fp atomics) -------------------
    // One warp per node. out[i] = bias + dout[i]*sum_f din[col]*y_src[col]
    //                                 + din[i]*sum_b dout[row]*y_dst[row]
    {
        const int lane = tid & 31;
        const int wpb = NT / 32;
        const int wid = blockIdx.x * wpb + (tid >> 5);
        const int wstride = nb * wpb;
        const float4* ys = (const float4*)g_y_src;
        const float4* yd = (const float4*)g_y_dst;

        // per-warp bias vector (uniform over nodes): lane covers dims 4*lane..+3
        int d = lane * 4;
        float4 bias4 = make_float4(
            ALPHA * __ldg(b_src + d + 0) + (1.0f - ALPHA) * __ldg(b_dst + d + 0),
            ALPHA * __ldg(b_src + d + 1) + (1.0f - ALPHA) * __ldg(b_dst + d + 1),
            ALPHA * __ldg(b_src + d + 2) + (1.0f - ALPHA) * __ldg(b_dst + d + 2),
            ALPHA * __ldg(b_src + d + 3) + (1.0f - ALPHA) * __ldg(b_dst + d + 3));

        for (int i = wid; i < N; i += wstride) {
            float4 accF = make_float4(0.f, 0.f, 0.f, 0.f);
            float4 accB = make_float4(0.f, 0.f, 0.f, 0.f);

            // forward: edges with row == i
            {
                int s = g_rs[i], n = g_outdeg[i];
                int k = 0;
                for (; k + 1 < n; k += 2) {
                    int c0 = g_fwd[s + k];
                    int c1 = g_fwd[s + k + 1];
                    float w0 = g_din[c0];
                    float w1 = g_din[c1];
                    float4 v0 = ys[c0 * 32 + lane];
                    float4 v1 = ys[c1 * 32 + lane];
                    accF.x += w0 * v0.x + w1 * v1.x;
                    accF.y += w0 * v0.y + w1 * v1.y;
                    accF.z += w0 * v0.z + w1 * v1.z;
                    accF.w += w0 * v0.w + w1 * v1.w;
                }
                if (k < n) {
                    int c0 = g_fwd[s + k];
                    float w0 = g_din[c0];
                    float4 v0 = ys[c0 * 32 + lane];
                    accF.x += w0 * v0.x; accF.y += w0 * v0.y;
                    accF.z += w0 * v0.z; accF.w += w0 * v0.w;
                }
            }
            // backward: edges with col == i
            {
                int s = g_cs[i], n = g_indeg[i];
                int k = 0;
                for (; k + 1 < n; k += 2) {
                    int r0 = g_bwd[s + k];
                    int r1 = g_bwd[s + k + 1];
                    float w0 = g_dout[r0];
                    float w1 = g_dout[r1];
                    float4 v0 = yd[r0 * 32 + lane];
                    float4 v1 = yd[r1 * 32 + lane];
                    accB.x += w0 * v0.x + w1 * v1.x;
                    accB.y += w0 * v0.y + w1 * v1.y;
                    accB.z += w0 * v0.z + w1 * v1.z;
                    accB.w += w0 * v0.w + w1 * v1.w;
                }
                if (k < n) {
                    int r0 = g_bwd[s + k];
                    float w0 = g_dout[r0];
                    float4 v0 = yd[r0 * 32 + lane];
                    accB.x += w0 * v0.x; accB.y += w0 * v0.y;
                    accB.z += w0 * v0.z; accB.w += w0 * v0.w;
                }
            }

            float di = g_dout[i];
            float dj = g_din[i];
            float4 o = make_float4(
                bias4.x + di * accF.x + dj * accB.x,
                bias4.y + di * accF.y + dj * accB.y,
                bias4.z + di * accF.z + dj * accB.z,
                bias4.w + di * accF.w + dj * accB.w);
            ((float4*)out)[i * 32 + lane] = o;
        }
    }
}

// ---------------- launch --------------------------------------------------------
extern "C" void kernel_launch(void* const* d_in, const int* in_sizes, int n_in,
                              void* d_out, int out_size) {
    // Size-based input identification (order-proof).
    int idx_x = -1, idx_e = -1;
    int idxW[2] = {-1, -1}, idxB[2] = {-1, -1};
    int nw = 0, nb_ = 0;
    for (int i = 0; i < n_in; i++) {
        int s = in_sizes[i];
        if (s == out_size && idx_x < 0) idx_x = i;
        else if (s == D * D && nw < 2)  idxW[nw++] = i;
        else if (s == D && nb_ < 2)     idxB[nb_++] = i;
        else if (idx_e < 0)             idx_e = i;
    }
    bool src_first = (idx_x < idx_e);

    const float* x      = (const float*)d_in[idx_x];
    const int*   ei_raw = (const int*)d_in[idx_e];
    const float* W_src  = (const float*)d_in[src_first ? idxW[0] : idxW[1]];
    const float* W_dst  = (const float*)d_in[src_first ? idxW[1] : idxW[0]];
    const float* b_src  = (const float*)d_in[src_first ? idxB[0] : idxB[1]];
    const float* b_dst  = (const float*)d_in[src_first ? idxB[1] : idxB[0]];
    float* out = (float*)d_out;

    int N = out_size / D;            // 50000
    int E = in_sizes[idx_e] / 2;     // 800000
    if (E > MAX_EDGES) E = MAX_EDGES;

    // ONE launch: all phases inside, separated by grid barriers.
    fused_kernel<<<NB, NT>>>(x, ei_raw, W_src, b_src, W_dst, b_dst, out, N, E);
}

// round 12
// speedup vs baseline: 1.4655x; 1.0982x over previous
#include <cuda_runtime.h>
#include <cuda_bf16.h>
#include <cstdint>

#define D 128
#define ALPHA 0.5f
#define MAX_NODES 50000
#define MAX_EDGES 800000
#define NB 296            // persistent grid: 2 CTAs/SM on 148 SMs, all co-resident
#define NT 256
#define GB 64             // graph blocks (block < GB); rest do GEMM

// ---------------- scratch (static device globals; no allocation) ----------------
__device__ float g_y_src[(size_t)MAX_NODES * D];   // alpha * (x @ W_src)
__device__ float g_y_dst[(size_t)MAX_NODES * D];   // (1-alpha) * (x @ W_dst)
__device__ int   g_outdeg[MAX_NODES];
__device__ int   g_indeg[MAX_NODES];
__device__ float g_dout[MAX_NODES];
__device__ float g_din[MAX_NODES];
__device__ int   g_ei[2 * MAX_EDGES];
__device__ int   g_rs[MAX_NODES];      // forward bucket start (by row)
__device__ int   g_cs[MAX_NODES];      // backward bucket start (by col)
__device__ int   g_rcur[MAX_NODES];
__device__ int   g_ccur[MAX_NODES];
__device__ int   g_fwd[MAX_EDGES];     // col indices, bucketed by row
__device__ int   g_bwd[MAX_EDGES];     // row indices, bucketed by col
__device__ unsigned g_base_f = 0, g_base_b = 0;

// global barrier (all NB blocks) + sub-barrier (GB graph blocks); generation-based
__device__ unsigned g_cnt = 0;
__device__ volatile unsigned g_gen = 0;
__device__ unsigned g_cnt2 = 0;
__device__ volatile unsigned g_gen2 = 0;

__device__ __forceinline__ void barrier_impl(unsigned* cnt, volatile unsigned* gen,
                                             int nblocks) {
    __syncthreads();
    if (threadIdx.x == 0) {
        unsigned my = *gen;
        __threadfence();
        if (atomicAdd(cnt, 1u) == (unsigned)(nblocks - 1)) {
            *cnt = 0;
            __threadfence();
            *gen = my + 1;
        } else {
            while (*gen == my) { }
        }
        __threadfence();
    }
    __syncthreads();
}
__device__ __forceinline__ void grid_barrier(int nb) { barrier_impl(&g_cnt, &g_gen, nb); }
__device__ __forceinline__ void sub_barrier()        { barrier_impl(&g_cnt2, &g_gen2, GB); }

// Dtype-agnostic index decode (exact for int32 and float32 encodings).
__device__ __forceinline__ int decode_idx(int v, int n) {
    if ((unsigned)v < (unsigned)n) return v;
    float f = __int_as_float(v);
    int r = (f > 0.0f) ? (int)f : 0;
    return ((unsigned)r < (unsigned)n) ? r : 0;
}

__device__ __forceinline__ uint32_t f2tf32(float f) {
    uint32_t u;
    asm("cvt.rna.tf32.f32 %0, %1;" : "=r"(u) : "f"(f));
    return u;
}

__device__ __forceinline__ void mma_tf32(float4& d,
                                         uint32_t a0, uint32_t a1, uint32_t a2, uint32_t a3,
                                         uint32_t b0, uint32_t b1) {
    asm volatile(
        "mma.sync.aligned.m16n8k8.row.col.f32.tf32.tf32.f32 "
        "{%0,%1,%2,%3}, {%4,%5,%6,%7}, {%8,%9}, {%0,%1,%2,%3};"
        : "+f"(d.x), "+f"(d.y), "+f"(d.z), "+f"(d.w)
        : "r"(a0), "r"(a1), "r"(a2), "r"(a3), "r"(b0), "r"(b1));
}

// GEMM tile: 64 rows x 128 cols, k-chunk 32, tf32 mma m16n8k8.
#define GEMM_TR 64
#define GEMM_KT 32
#define XSP 33            // Xs row stride (pad vs bank conflicts)
#define WSP 132           // Ws row stride (pad, multiple of 4 for float4 fills)

__global__ void __launch_bounds__(NT, 2)
fused_kernel(const float* __restrict__ x,
             const int* __restrict__ ei_raw,
             const float* __restrict__ W_src, const float* __restrict__ b_src,
             const float* __restrict__ W_dst, const float* __restrict__ b_dst,
             float* __restrict__ out,
             int N, int E) {
    __shared__ float Ws[GEMM_KT * WSP];   // 16.9 KB
    __shared__ float Xs[GEMM_TR * XSP];   // 8.4 KB

    const int tid = threadIdx.x;
    const int nb = gridDim.x;
    const int bid = blockIdx.x;

    if (bid < GB) {
        // ================= GRAPH BLOCKS: decode -> degrees -> CSR =================
        const int gtid = bid * NT + tid;
        const int gstride = GB * NT;

        for (int i = gtid; i < N; i += gstride) {
            g_outdeg[i] = 0;
            g_indeg[i] = 0;
        }
        if (gtid == 0) { g_base_f = 0; g_base_b = 0; }
        sub_barrier();

        for (int i = gtid; i < 2 * E; i += gstride) {
            int v = decode_idx(ei_raw[i], N);
            g_ei[i] = v;
            if (i < E) atomicAdd(&g_outdeg[v], 1);
            else       atomicAdd(&g_indeg[v], 1);
        }
        sub_barrier();

        for (int i = gtid; i < N; i += gstride) {
            int od = g_outdeg[i];
            int id = g_indeg[i];
            g_dout[i] = (od > 0) ? rsqrtf((float)od) : 0.0f;
            g_din[i]  = (id > 0) ? rsqrtf((float)id) : 0.0f;
            int rs = (int)atomicAdd(&g_base_f, (unsigned)od);
            int cs = (int)atomicAdd(&g_base_b, (unsigned)id);
            g_rs[i] = rs;  g_rcur[i] = rs;
            g_cs[i] = cs;  g_ccur[i] = cs;
        }
        sub_barrier();

        for (int e = gtid; e < E; e += gstride) {
            int row = g_ei[e];
            int col = g_ei[E + e];
            g_fwd[atomicAdd(&g_rcur[row], 1)] = col;
            g_bwd[atomicAdd(&g_ccur[col], 1)] = row;
        }
    } else {
        // ================= GEMM BLOCKS: tf32 tensor-core GEMMs ====================
        const int tiles = (N + GEMM_TR - 1) / GEMM_TR;
        const int lane = tid & 31;
        const int warp = tid >> 5;
        const int gid = lane >> 2;       // 0..7
        const int tig = lane & 3;        // 0..3
        const int m0 = (warp & 3) * 16;  // warp's m offset in tile
        const int n0 = (warp >> 2) * 64; // warp's n offset

        for (int job = bid - GB; job < 2 * tiles; job += nb - GB) {
            const bool is_src = (job < tiles);
            const float* W = is_src ? W_src : W_dst;
            float* Y       = is_src ? g_y_src : g_y_dst;
            const float scale = is_src ? ALPHA : (1.0f - ALPHA);
            const int row0 = (is_src ? job : job - tiles) * GEMM_TR;

            float4 acc[8];
#pragma unroll
            for (int t = 0; t < 8; t++) acc[t] = make_float4(0.f, 0.f, 0.f, 0.f);

            for (int kt = 0; kt < D; kt += GEMM_KT) {
                // load W chunk [32][128] via float4
#pragma unroll
                for (int i = tid; i < GEMM_KT * (D / 4); i += NT) {
                    int kk = i >> 5, d4 = i & 31;
                    float4 v = ((const float4*)(W + (kt + kk) * D))[d4];
                    *(float4*)&Ws[kk * WSP + d4 * 4] = v;
                }
                // load X chunk [64][32] via float4 (scalar smem stores, padded)
#pragma unroll
                for (int i = tid; i < GEMM_TR * (GEMM_KT / 4); i += NT) {
                    int r = i >> 3, c4 = i & 7;
                    int gr = row0 + r;
                    float4 v = (gr < N)
                        ? ((const float4*)(x + (size_t)gr * D + kt))[c4]
                        : make_float4(0.f, 0.f, 0.f, 0.f);
                    float* p = &Xs[r * XSP + c4 * 4];
                    p[0] = v.x; p[1] = v.y; p[2] = v.z; p[3] = v.w;
                }
                __syncthreads();

#pragma unroll
                for (int ks = 0; ks < GEMM_KT; ks += 8) {
                    uint32_t a0 = f2tf32(Xs[(m0 + gid)     * XSP + ks + tig]);
                    uint32_t a1 = f2tf32(Xs[(m0 + gid + 8) * XSP + ks + tig]);
                    uint32_t a2 = f2tf32(Xs[(m0 + gid)     * XSP + ks + tig + 4]);
                    uint32_t a3 = f2tf32(Xs[(m0 + gid + 8) * XSP + ks + tig + 4]);
#pragma unroll
                    for (int t = 0; t < 8; t++) {
                        uint32_t b0 = f2tf32(Ws[(ks + tig)     * WSP + n0 + t * 8 + gid]);
                        uint32_t b1 = f2tf32(Ws[(ks + tig + 4) * WSP + n0 + t * 8 + gid]);
                        mma_tf32(acc[t], a0, a1, a2, a3, b0, b1);
                    }
                }
                __syncthreads();
            }

            // store: c0,c1 -> (row m0+gid, cols 2*tig,2*tig+1); c2,c3 -> row +8
            int r0 = row0 + m0 + gid;
            int r1 = r0 + 8;
#pragma unroll
            for (int t = 0; t < 8; t++) {
                int col = n0 + t * 8 + 2 * tig;
                if (r0 < N) {
                    float2 v = make_float2(scale * acc[t].x, scale * acc[t].y);
                    *(float2*)&Y[(size_t)r0 * D + col] = v;
                }
                if (r1 < N) {
                    float2 v = make_float2(scale * acc[t].z, scale * acc[t].w);
                    *(float2*)&Y[(size_t)r1 * D + col] = v;
                }
            }
        }
    }

    grid_barrier(nb);

    // ================= ALL BLOCKS: per-node gather (no fp atomics) ================
    {
        const int lane = tid & 31;
        const int wpb = NT / 32;
        const int wid = bid * wpb + (tid >> 5);
        const int wstride = nb * wpb;
        const float4* ys = (const float4*)g_y_src;
        const float4* yd = (const float4*)g_y_dst;

        int d = lane * 4;
        float4 bias4 = make_float4(
            ALPHA * __ldg(b_src + d + 0) + (1.0f - ALPHA) * __ldg(b_dst + d + 0),
            ALPHA * __ldg(b_src + d + 1) + (1.0f - ALPHA) * __ldg(b_dst + d + 1),
            ALPHA * __ldg(b_src + d + 2) + (1.0f - ALPHA) * __ldg(b_dst + d + 2),
            ALPHA * __ldg(b_src + d + 3) + (1.0f - ALPHA) * __ldg(b_dst + d + 3));

        for (int i = wid; i < N; i += wstride) {
            float4 accF = make_float4(0.f, 0.f, 0.f, 0.f);
            float4 accB = make_float4(0.f, 0.f, 0.f, 0.f);
            {
                int s = g_rs[i], n = g_outdeg[i];
                int k = 0;
                for (; k + 1 < n; k += 2) {
                    int c0 = g_fwd[s + k];
                    int c1 = g_fwd[s + k + 1];
                    float w0 = g_din[c0];
                    float w1 = g_din[c1];
                    float4 v0 = ys[c0 * 32 + lane];
                    float4 v1 = ys[c1 * 32 + lane];
                    accF.x += w0 * v0.x + w1 * v1.x;
                    accF.y += w0 * v0.y + w1 * v1.y;
                    accF.z += w0 * v0.z + w1 * v1.z;
                    accF.w += w0 * v0.w + w1 * v1.w;
                }
                if (k < n) {
                    int c0 = g_fwd[s + k];
                    float w0 = g_din[c0];
                    float4 v0 = ys[c0 * 32 + lane];
                    accF.x += w0 * v0.x; accF.y += w0 * v0.y;
                    accF.z += w0 * v0.z; accF.w += w0 * v0.w;
                }
            }
            {
                int s = g_cs[i], n = g_indeg[i];
                int k = 0;
                for (; k + 1 < n; k += 2) {
                    int r0 = g_bwd[s + k];
                    int r1 = g_bwd[s + k + 1];
                    float w0 = g_dout[r0];
                    float w1 = g_dout[r1];
                    float4 v0 = yd[r0 * 32 + lane];
                    float4 v1 = yd[r1 * 32 + lane];
                    accB.x += w0 * v0.x + w1 * v1.x;
                    accB.y += w0 * v0.y + w1 * v1.y;
                    accB.z += w0 * v0.z + w1 * v1.z;
                    accB.w += w0 * v0.w + w1 * v1.w;
                }
                if (k < n) {
                    int r0 = g_bwd[s + k];
                    float w0 = g_dout[r0];
                    float4 v0 = yd[r0 * 32 + lane];
                    accB.x += w0 * v0.x; accB.y += w0 * v0.y;
                    accB.z += w0 * v0.z; accB.w += w0 * v0.w;
                }
            }
            float di = g_dout[i];
            float dj = g_din[i];
            float4 o = make_float4(
                bias4.x + di * accF.x + dj * accB.x,
                bias4.y + di * accF.y + dj * accB.y,
                bias4.z + di * accF.z + dj * accB.z,
                bias4.w + di * accF.w + dj * accB.w);
            ((float4*)out)[i * 32 + lane] = o;
        }
    }
}

// ---------------- launch --------------------------------------------------------
extern "C" void kernel_launch(void* const* d_in, const int* in_sizes, int n_in,
                              void* d_out, int out_size) {
    // Size-based input identification (order-proof).
    int idx_x = -1, idx_e = -1;
    int idxW[2] = {-1, -1}, idxB[2] = {-1, -1};
    int nw = 0, nb_ = 0;
    for (int i = 0; i < n_in; i++) {
        int s = in_sizes[i];
        if (s == out_size && idx_x < 0) idx_x = i;
        else if (s == D * D && nw < 2)  idxW[nw++] = i;
        else if (s == D && nb_ < 2)     idxB[nb_++] = i;
        else if (idx_e < 0)             idx_e = i;
    }
    bool src_first = (idx_x < idx_e);

    const float* x      = (const float*)d_in[idx_x];
    const int*   ei_raw = (const int*)d_in[idx_e];
    const float* W_src  = (const float*)d_in[src_first ? idxW[0] : idxW[1]];
    const float* W_dst  = (const float*)d_in[src_first ? idxW[1] : idxW[0]];
    const float* b_src  = (const float*)d_in[src_first ? idxB[0] : idxB[1]];
    const float* b_dst  = (const float*)d_in[src_first ? idxB[1] : idxB[0]];
    float* out = (float*)d_out;

    int N = out_size / D;            // 50000
    int E = in_sizes[idx_e] / 2;     // 800000
    if (E > MAX_EDGES) E = MAX_EDGES;

    // ONE launch: graph blocks build CSR concurrently with tf32 GEMM blocks.
    fused_kernel<<<NB, NT>>>(x, ei_raw, W_src, b_src, W_dst, b_dst, out, N, E);
}

// round 13
// speedup vs baseline: 1.8474x; 1.2606x over previous
#include <cuda_runtime.h>
#include <cuda_bf16.h>
#include <cstdint>

#define D 128
#define ALPHA 0.5f
#define MAX_NODES 50000
#define MAX_EDGES 800000
#define NB 296            // persistent grid: 2 CTAs/SM on 148 SMs, all co-resident
#define NT 256
#define GB 96             // graph blocks (block < GB); rest do GEMM

// ---------------- scratch (static device globals; no allocation) ----------------
__device__ float g_y_src[(size_t)MAX_NODES * D];   // alpha * (x @ W_src)
__device__ float g_y_dst[(size_t)MAX_NODES * D];   // (1-alpha) * (x @ W_dst)
__device__ int   g_outdeg[MAX_NODES];
__device__ int   g_indeg[MAX_NODES];
__device__ float g_dout[MAX_NODES];
__device__ float g_din[MAX_NODES];
__device__ int   g_ei[2 * MAX_EDGES];
__device__ int   g_rs[MAX_NODES];      // forward bucket start (by row)
__device__ int   g_cs[MAX_NODES];      // backward bucket start (by col)
__device__ int   g_rcur[MAX_NODES];
__device__ int   g_ccur[MAX_NODES];
__device__ int   g_fwd[MAX_EDGES];     // col indices, bucketed by row
__device__ int   g_bwd[MAX_EDGES];     // row indices, bucketed by col
__device__ unsigned g_base_f = 0, g_base_b = 0;

// global barrier (all NB blocks) + sub-barrier (GB graph blocks); generation-based
__device__ unsigned g_cnt = 0;
__device__ volatile unsigned g_gen = 0;
__device__ unsigned g_cnt2 = 0;
__device__ volatile unsigned g_gen2 = 0;

__device__ __forceinline__ void barrier_impl(unsigned* cnt, volatile unsigned* gen,
                                             int nblocks) {
    __syncthreads();
    if (threadIdx.x == 0) {
        unsigned my = *gen;
        __threadfence();
        if (atomicAdd(cnt, 1u) == (unsigned)(nblocks - 1)) {
            *cnt = 0;
            __threadfence();
            *gen = my + 1;
        } else {
            while (*gen == my) { }
        }
        __threadfence();
    }
    __syncthreads();
}
__device__ __forceinline__ void grid_barrier(int nb) { barrier_impl(&g_cnt, &g_gen, nb); }
__device__ __forceinline__ void sub_barrier()        { barrier_impl(&g_cnt2, &g_gen2, GB); }

// Dtype-agnostic index decode (exact for int32 and float32 encodings).
__device__ __forceinline__ int decode_idx(int v, int n) {
    if ((unsigned)v < (unsigned)n) return v;
    float f = __int_as_float(v);
    int r = (f > 0.0f) ? (int)f : 0;
    return ((unsigned)r < (unsigned)n) ? r : 0;
}

__device__ __forceinline__ uint32_t f2tf32(float f) {
    uint32_t u;
    asm("cvt.rna.tf32.f32 %0, %1;" : "=r"(u) : "f"(f));
    return u;
}

__device__ __forceinline__ void mma_tf32(float4& d,
                                         uint32_t a0, uint32_t a1, uint32_t a2, uint32_t a3,
                                         uint32_t b0, uint32_t b1) {
    asm volatile(
        "mma.sync.aligned.m16n8k8.row.col.f32.tf32.tf32.f32 "
        "{%0,%1,%2,%3}, {%4,%5,%6,%7}, {%8,%9}, {%0,%1,%2,%3};"
        : "+f"(d.x), "+f"(d.y), "+f"(d.z), "+f"(d.w)
        : "r"(a0), "r"(a1), "r"(a2), "r"(a3), "r"(b0), "r"(b1));
}

// GEMM tile: 64 rows x 128 cols, k-chunk 32, tf32 mma m16n8k8.
// Conflict-free strides: WSP%32==8 -> bank = 8*tig+gid (all distinct);
//                        XSP%32==4 -> bank = 4*gid+tig (all distinct).
#define GEMM_TR 64
#define GEMM_KT 32
#define XSP 36
#define WSP 136

__global__ void __launch_bounds__(NT, 2)
fused_kernel(const float* __restrict__ x,
             const int* __restrict__ ei_raw,
             const float* __restrict__ W_src, const float* __restrict__ b_src,
             const float* __restrict__ W_dst, const float* __restrict__ b_dst,
             float* __restrict__ out,
             int N, int E) {
    __shared__ uint32_t Ws[GEMM_KT * WSP];   // 17.4 KB (tf32 bits)
    __shared__ uint32_t Xs[GEMM_TR * XSP];   // 9.2 KB  (tf32 bits)

    const int tid = threadIdx.x;
    const int nb = gridDim.x;
    const int bid = blockIdx.x;

    if (bid < GB) {
        // ================= GRAPH BLOCKS: decode -> degrees -> CSR =================
        const int gtid = bid * NT + tid;
        const int gstride = GB * NT;

        for (int i = gtid; i < N; i += gstride) {
            g_outdeg[i] = 0;
            g_indeg[i] = 0;
        }
        if (gtid == 0) { g_base_f = 0; g_base_b = 0; }
        sub_barrier();

        for (int i = gtid; i < 2 * E; i += gstride) {
            int v = decode_idx(ei_raw[i], N);
            g_ei[i] = v;
            if (i < E) atomicAdd(&g_outdeg[v], 1);
            else       atomicAdd(&g_indeg[v], 1);
        }
        sub_barrier();

        for (int i = gtid; i < N; i += gstride) {
            int od = g_outdeg[i];
            int id = g_indeg[i];
            g_dout[i] = (od > 0) ? rsqrtf((float)od) : 0.0f;
            g_din[i]  = (id > 0) ? rsqrtf((float)id) : 0.0f;
            int rs = (int)atomicAdd(&g_base_f, (unsigned)od);
            int cs = (int)atomicAdd(&g_base_b, (unsigned)id);
            g_rs[i] = rs;  g_rcur[i] = rs;
            g_cs[i] = cs;  g_ccur[i] = cs;
        }
        sub_barrier();

        for (int e = gtid; e < E; e += gstride) {
            int row = g_ei[e];
            int col = g_ei[E + e];
            g_fwd[atomicAdd(&g_rcur[row], 1)] = col;
            g_bwd[atomicAdd(&g_ccur[col], 1)] = row;
        }
    } else {
        // ================= GEMM BLOCKS: tf32 tensor-core GEMMs ====================
        const int tiles = (N + GEMM_TR - 1) / GEMM_TR;
        const int lane = tid & 31;
        const int warp = tid >> 5;
        const int gid = lane >> 2;       // 0..7
        const int tig = lane & 3;        // 0..3
        const int m0 = (warp & 3) * 16;  // warp's m offset in tile
        const int n0 = (warp >> 2) * 64; // warp's n offset

        for (int job = bid - GB; job < 2 * tiles; job += nb - GB) {
            const bool is_src = (job < tiles);
            const float* W = is_src ? W_src : W_dst;
            float* Y       = is_src ? g_y_src : g_y_dst;
            const float scale = is_src ? ALPHA : (1.0f - ALPHA);
            const int row0 = (is_src ? job : job - tiles) * GEMM_TR;

            float4 acc[8];
#pragma unroll
            for (int t = 0; t < 8; t++) acc[t] = make_float4(0.f, 0.f, 0.f, 0.f);

            for (int kt = 0; kt < D; kt += GEMM_KT) {
                // load W chunk [32][128], convert to tf32 at fill
#pragma unroll
                for (int i = tid; i < GEMM_KT * (D / 4); i += NT) {
                    int kk = i >> 5, d4 = i & 31;
                    float4 v = ((const float4*)(W + (kt + kk) * D))[d4];
                    uint4 u = make_uint4(f2tf32(v.x), f2tf32(v.y),
                                         f2tf32(v.z), f2tf32(v.w));
                    *(uint4*)&Ws[kk * WSP + d4 * 4] = u;
                }
                // load X chunk [64][32], convert to tf32 at fill
#pragma unroll
                for (int i = tid; i < GEMM_TR * (GEMM_KT / 4); i += NT) {
                    int r = i >> 3, c4 = i & 7;
                    int gr = row0 + r;
                    float4 v = (gr < N)
                        ? ((const float4*)(x + (size_t)gr * D + kt))[c4]
                        : make_float4(0.f, 0.f, 0.f, 0.f);
                    uint4 u = make_uint4(f2tf32(v.x), f2tf32(v.y),
                                         f2tf32(v.z), f2tf32(v.w));
                    *(uint4*)&Xs[r * XSP + c4 * 4] = u;
                }
                __syncthreads();

#pragma unroll
                for (int ks = 0; ks < GEMM_KT; ks += 8) {
                    uint32_t a0 = Xs[(m0 + gid)     * XSP + ks + tig];
                    uint32_t a1 = Xs[(m0 + gid + 8) * XSP + ks + tig];
                    uint32_t a2 = Xs[(m0 + gid)     * XSP + ks + tig + 4];
                    uint32_t a3 = Xs[(m0 + gid + 8) * XSP + ks + tig + 4];
#pragma unroll
                    for (int t = 0; t < 8; t++) {
                        uint32_t b0 = Ws[(ks + tig)     * WSP + n0 + t * 8 + gid];
                        uint32_t b1 = Ws[(ks + tig + 4) * WSP + n0 + t * 8 + gid];
                        mma_tf32(acc[t], a0, a1, a2, a3, b0, b1);
                    }
                }
                __syncthreads();
            }

            // store: c0,c1 -> (row m0+gid, cols 2*tig,2*tig+1); c2,c3 -> row +8
            int r0 = row0 + m0 + gid;
            int r1 = r0 + 8;
#pragma unroll
            for (int t = 0; t < 8; t++) {
                int col = n0 + t * 8 + 2 * tig;
                if (r0 < N) {
                    float2 v = make_float2(scale * acc[t].x, scale * acc[t].y);
                    *(float2*)&Y[(size_t)r0 * D + col] = v;
                }
                if (r1 < N) {
                    float2 v = make_float2(scale * acc[t].z, scale * acc[t].w);
                    *(float2*)&Y[(size_t)r1 * D + col] = v;
                }
            }
        }
    }

    grid_barrier(nb);

    // ================= ALL BLOCKS: per-node gather (no fp atomics) ================
    {
        const int lane = tid & 31;
        const int wpb = NT / 32;
        const int wid = bid * wpb + (tid >> 5);
        const int wstride = nb * wpb;
        const float4* ys = (const float4*)g_y_src;
        const float4* yd = (const float4*)g_y_dst;

        int d = lane * 4;
        float4 bias4 = make_float4(
            ALPHA * __ldg(b_src + d + 0) + (1.0f - ALPHA) * __ldg(b_dst + d + 0),
            ALPHA * __ldg(b_src + d + 1) + (1.0f - ALPHA) * __ldg(b_dst + d + 1),
            ALPHA * __ldg(b_src + d + 2) + (1.0f - ALPHA) * __ldg(b_dst + d + 2),
            ALPHA * __ldg(b_src + d + 3) + (1.0f - ALPHA) * __ldg(b_dst + d + 3));

        for (int i = wid; i < N; i += wstride) {
            float4 accF = make_float4(0.f, 0.f, 0.f, 0.f);
            float4 accB = make_float4(0.f, 0.f, 0.f, 0.f);

            // forward: edges with row == i (4-wide unroll, batched loads)
            {
                int s = g_rs[i], n = g_outdeg[i];
                int k = 0;
                for (; k + 3 < n; k += 4) {
                    int c0 = g_fwd[s + k];
                    int c1 = g_fwd[s + k + 1];
                    int c2 = g_fwd[s + k + 2];
                    int c3 = g_fwd[s + k + 3];
                    float w0 = g_din[c0], w1 = g_din[c1];
                    float w2 = g_din[c2], w3 = g_din[c3];
                    float4 v0 = ys[c0 * 32 + lane];
                    float4 v1 = ys[c1 * 32 + lane];
                    float4 v2 = ys[c2 * 32 + lane];
                    float4 v3 = ys[c3 * 32 + lane];
                    accF.x += w0 * v0.x + w1 * v1.x + w2 * v2.x + w3 * v3.x;
                    accF.y += w0 * v0.y + w1 * v1.y + w2 * v2.y + w3 * v3.y;
                    accF.z += w0 * v0.z + w1 * v1.z + w2 * v2.z + w3 * v3.z;
                    accF.w += w0 * v0.w + w1 * v1.w + w2 * v2.w + w3 * v3.w;
                }
                for (; k < n; k++) {
                    int c0 = g_fwd[s + k];
                    float w0 = g_din[c0];
                    float4 v0 = ys[c0 * 32 + lane];
                    accF.x += w0 * v0.x; accF.y += w0 * v0.y;
                    accF.z += w0 * v0.z; accF.w += w0 * v0.w;
                }
            }
            // backward: edges with col == i
            {
                int s = g_cs[i], n = g_indeg[i];
                int k = 0;
                for (; k + 3 < n; k += 4) {
                    int r0 = g_bwd[s + k];
                    int r1 = g_bwd[s + k + 1];
                    int r2 = g_bwd[s + k + 2];
                    int r3 = g_bwd[s + k + 3];
                    float w0 = g_dout[r0], w1 = g_dout[r1];
                    float w2 = g_dout[r2], w3 = g_dout[r3];
                    float4 v0 = yd[r0 * 32 + lane];
                    float4 v1 = yd[r1 * 32 + lane];
                    float4 v2 = yd[r2 * 32 + lane];
                    float4 v3 = yd[r3 * 32 + lane];
                    accB.x += w0 * v0.x + w1 * v1.x + w2 * v2.x + w3 * v3.x;
                    accB.y += w0 * v0.y + w1 * v1.y + w2 * v2.y + w3 * v3.y;
                    accB.z += w0 * v0.z + w1 * v1.z + w2 * v2.z + w3 * v3.z;
                    accB.w += w0 * v0.w + w1 * v1.w + w2 * v2.w + w3 * v3.w;
                }
                for (; k < n; k++) {
                    int r0 = g_bwd[s + k];
                    float w0 = g_dout[r0];
                    float4 v0 = yd[r0 * 32 + lane];
                    accB.x += w0 * v0.x; accB.y += w0 * v0.y;
                    accB.z += w0 * v0.z; accB.w += w0 * v0.w;
                }
            }

            float di = g_dout[i];
            float dj = g_din[i];
            float4 o = make_float4(
                bias4.x + di * accF.x + dj * accB.x,
                bias4.y + di * accF.y + dj * accB.y,
                bias4.z + di * accF.z + dj * accB.z,
                bias4.w + di * accF.w + dj * accB.w);
            ((float4*)out)[i * 32 + lane] = o;
        }
    }
}

// ---------------- launch --------------------------------------------------------
extern "C" void kernel_launch(void* const* d_in, const int* in_sizes, int n_in,
                              void* d_out, int out_size) {
    // Size-based input identification (order-proof).
    int idx_x = -1, idx_e = -1;
    int idxW[2] = {-1, -1}, idxB[2] = {-1, -1};
    int nw = 0, nb_ = 0;
    for (int i = 0; i < n_in; i++) {
        int s = in_sizes[i];
        if (s == out_size && idx_x < 0) idx_x = i;
        else if (s == D * D && nw < 2)  idxW[nw++] = i;
        else if (s == D && nb_ < 2)     idxB[nb_++] = i;
        else if (idx_e < 0)             idx_e = i;
    }
    bool src_first = (idx_x < idx_e);

    const float* x      = (const float*)d_in[idx_x];
    const int*   ei_raw = (const int*)d_in[idx_e];
    const float* W_src  = (const float*)d_in[src_first ? idxW[0] : idxW[1]];
    const float* W_dst  = (const float*)d_in[src_first ? idxW[1] : idxW[0]];
    const float* b_src  = (const float*)d_in[src_first ? idxB[0] : idxB[1]];
    const float* b_dst  = (const float*)d_in[src_first ? idxB[1] : idxB[0]];
    float* out = (float*)d_out;

    int N = out_size / D;            // 50000
    int E = in_sizes[idx_e] / 2;     // 800000
    if (E > MAX_EDGES) E = MAX_EDGES;

    // ONE launch: graph blocks build CSR concurrently with tf32 GEMM blocks.
    fused_kernel<<<NB, NT>>>(x, ei_raw, W_src, b_src, W_dst, b_dst, out, N, E);
}